// round 1
// baseline (speedup 1.0000x reference)
#include <cuda_runtime.h>
#include <math.h>

#define B_  4
#define H_  16
#define N_  2048
#define Dh_ 64
#define DIM_ 1024
#define M_  (B_*N_)          // 8192 rows
#define ELEMS (B_*H_*N_*Dh_) // 8388608

__device__ float g_q[ELEMS];
__device__ float g_k[ELEMS];
__device__ float g_v[ELEMS];
__device__ float g_o[ELEMS];

// ---------------------------------------------------------------------------
// Tiled SGEMM: C[M x Ncols] = A[M x 1024] @ W[1024 x Ncols]
// MODE 0: A = x, epilogue scatters to g_q (scaled by 1/8)
// MODE 1: A = x, epilogue scatters cols<1024 -> g_k, else -> g_v
// MODE 2: A gathered from g_o (head-major), epilogue adds bias -> Cout
// BM=BN=128, BK=8, 256 threads, 8x8 per thread in 2x2 quadrants of 4x4.
// ---------------------------------------------------------------------------
template<int MODE>
__global__ void __launch_bounds__(256)
gemm_k(const float* __restrict__ A, const float* __restrict__ W,
       float* __restrict__ Cout, const float* __restrict__ bias, int Ncols)
{
    __shared__ __align__(16) float As[8][132];
    __shared__ __align__(16) float Bs[8][128];

    const int tid = threadIdx.x;
    const int m0 = blockIdx.y * 128;
    const int n0 = blockIdx.x * 128;
    const int ty = tid >> 4;       // 0..15
    const int tx = tid & 15;       // 0..15

    const int lm = tid >> 1;       // 0..127  (A tile row)
    const int lh = (tid & 1) * 4;  // 0 or 4  (k offset)
    const int bk = tid >> 5;       // 0..7    (B tile row)
    const int bc = (tid & 31) * 4; // 0..124  (B tile col)

    float acc[2][2][4][4];
    #pragma unroll
    for (int a0 = 0; a0 < 2; a0++)
        #pragma unroll
        for (int a1 = 0; a1 < 2; a1++)
            #pragma unroll
            for (int i = 0; i < 4; i++)
                #pragma unroll
                for (int j = 0; j < 4; j++) acc[a0][a1][i][j] = 0.f;

    for (int k0 = 0; k0 < DIM_; k0 += 8) {
        float4 av;
        if (MODE == 2) {
            int row = m0 + lm;
            int k = k0 + lh;
            int b = row >> 11, n = row & 2047, h = k >> 6, d = k & 63;
            av = *(const float4*)&g_o[(((size_t)((b << 4) + h)) * N_ + n) * Dh_ + d];
        } else {
            av = *(const float4*)&A[(size_t)(m0 + lm) * DIM_ + k0 + lh];
        }
        As[lh + 0][lm] = av.x;
        As[lh + 1][lm] = av.y;
        As[lh + 2][lm] = av.z;
        As[lh + 3][lm] = av.w;
        *(float4*)&Bs[bk][bc] = *(const float4*)&W[(size_t)(k0 + bk) * Ncols + n0 + bc];
        __syncthreads();

        #pragma unroll
        for (int kk = 0; kk < 8; kk++) {
            float a[2][4], b[2][4];
            *(float4*)a[0] = *(const float4*)&As[kk][ty * 4];
            *(float4*)a[1] = *(const float4*)&As[kk][64 + ty * 4];
            *(float4*)b[0] = *(const float4*)&Bs[kk][tx * 4];
            *(float4*)b[1] = *(const float4*)&Bs[kk][64 + tx * 4];
            #pragma unroll
            for (int rh = 0; rh < 2; rh++)
                #pragma unroll
                for (int ch = 0; ch < 2; ch++)
                    #pragma unroll
                    for (int i = 0; i < 4; i++)
                        #pragma unroll
                        for (int j = 0; j < 4; j++)
                            acc[rh][ch][i][j] += a[rh][i] * b[ch][j];
        }
        __syncthreads();
    }

    // epilogue
    #pragma unroll
    for (int rh = 0; rh < 2; rh++) {
        #pragma unroll
        for (int i = 0; i < 4; i++) {
            const int gm = m0 + rh * 64 + ty * 4 + i;
            #pragma unroll
            for (int ch = 0; ch < 2; ch++) {
                const int gn = n0 + ch * 64 + tx * 4;
                if (MODE == 2) {
                    float4 bv = *(const float4*)&bias[gn];
                    float4 v;
                    v.x = acc[rh][ch][i][0] + bv.x;
                    v.y = acc[rh][ch][i][1] + bv.y;
                    v.z = acc[rh][ch][i][2] + bv.z;
                    v.w = acc[rh][ch][i][3] + bv.w;
                    *(float4*)&Cout[(size_t)gm * DIM_ + gn] = v;
                } else if (MODE == 0) {
                    int b = gm >> 11, n = gm & 2047, h = gn >> 6, d = gn & 63;
                    float4 v;
                    v.x = acc[rh][ch][i][0] * 0.125f;
                    v.y = acc[rh][ch][i][1] * 0.125f;
                    v.z = acc[rh][ch][i][2] * 0.125f;
                    v.w = acc[rh][ch][i][3] * 0.125f;
                    *(float4*)&g_q[(((size_t)((b << 4) + h)) * N_ + n) * Dh_ + d] = v;
                } else {
                    int b = gm >> 11, n = gm & 2047;
                    int cc = gn & 1023;
                    int h = cc >> 6, d = cc & 63;
                    float* dst = (gn < 1024) ? g_k : g_v;
                    float4 v;
                    v.x = acc[rh][ch][i][0];
                    v.y = acc[rh][ch][i][1];
                    v.z = acc[rh][ch][i][2];
                    v.w = acc[rh][ch][i][3];
                    *(float4*)&dst[(((size_t)((b << 4) + h)) * N_ + n) * Dh_ + d] = v;
                }
            }
        }
    }
}

// ---------------------------------------------------------------------------
// Flash attention, causal, fp32. One block = 64 query rows of one (b,h).
// grid = (N/64, B*H), 256 threads.
// smem: Qt[64][68] (d-major), Kt[64][68] (d-major), Ps[64][68] (= S^T),
//       Vs[64][64], stats.
// ---------------------------------------------------------------------------
#define FL_SMEM_FLOATS (3*64*68 + 64*64 + 3*64 + 2*4*64)
#define FL_SMEM_BYTES  (FL_SMEM_FLOATS * 4)

__global__ void __launch_bounds__(256) flash_k()
{
    extern __shared__ __align__(16) float sm[];
    float* Qt = sm;                  // [64][68]   Qt[d*68 + r]
    float* Kt = Qt + 64 * 68;        // [64][68]   Kt[d*68 + c]
    float* Ps = Kt + 64 * 68;        // [64][68]   Ps[c*68 + r] = S[r][c]
    float* Vs = Ps + 64 * 68;        // [64][64]   Vs[c*64 + d]
    float* rm = Vs + 64 * 64;        // [64] running max
    float* rl = rm + 64;             // [64] running sum
    float* ral = rl + 64;            // [64] alpha
    float* qmax = ral + 64;          // [4][64]
    float* qsum = qmax + 256;        // [4][64]

    const int tid = threadIdx.x;
    const int bh = blockIdx.y;
    const int m0 = blockIdx.x * 64;

    const float* qb = g_q + (size_t)bh * N_ * Dh_;
    const float* kb = g_k + (size_t)bh * N_ * Dh_;
    const float* vb = g_v + (size_t)bh * N_ * Dh_;
    float* ob = g_o + (size_t)bh * N_ * Dh_;

    // load Q transposed (scale already folded in at projection)
    {
        const int r = tid >> 2;
        const int dbase = (tid & 3) * 4;
        #pragma unroll
        for (int dd = 0; dd < 4; dd++) {
            int d4 = dbase + dd * 16;
            float4 qv = *(const float4*)&qb[(size_t)(m0 + r) * Dh_ + d4];
            Qt[(d4 + 0) * 68 + r] = qv.x;
            Qt[(d4 + 1) * 68 + r] = qv.y;
            Qt[(d4 + 2) * 68 + r] = qv.z;
            Qt[(d4 + 3) * 68 + r] = qv.w;
        }
    }
    if (tid < 64) { rm[tid] = -1e30f; rl[tid] = 0.f; }

    const int ty = tid >> 4;   // 0..15 -> query rows ty*4..+3
    const int tx = tid & 15;   // 0..15 -> key cols / d cols tx*4..+3
    float o[4][4];
    #pragma unroll
    for (int i = 0; i < 4; i++)
        #pragma unroll
        for (int j = 0; j < 4; j++) o[i][j] = 0.f;

    const int ntiles = blockIdx.x + 1;
    for (int t = 0; t < ntiles; t++) {
        const int j0 = t * 64;
        __syncthreads();   // protect Kt/Vs/Ps reuse across iterations
        // load K (transposed) and V (row-major)
        {
            const int r = tid >> 2;
            const int dbase = (tid & 3) * 4;
            #pragma unroll
            for (int dd = 0; dd < 4; dd++) {
                int d4 = dbase + dd * 16;
                float4 kv4 = *(const float4*)&kb[(size_t)(j0 + r) * Dh_ + d4];
                Kt[(d4 + 0) * 68 + r] = kv4.x;
                Kt[(d4 + 1) * 68 + r] = kv4.y;
                Kt[(d4 + 2) * 68 + r] = kv4.z;
                Kt[(d4 + 3) * 68 + r] = kv4.w;
                *(float4*)&Vs[r * 64 + d4] = *(const float4*)&vb[(size_t)(j0 + r) * Dh_ + d4];
            }
        }
        __syncthreads();

        // S = Q K^T  (4x4 micro per thread)
        float s[4][4];
        #pragma unroll
        for (int i = 0; i < 4; i++)
            #pragma unroll
            for (int j = 0; j < 4; j++) s[i][j] = 0.f;
        #pragma unroll
        for (int d = 0; d < 64; d++) {
            float4 a = *(const float4*)&Qt[d * 68 + ty * 4];
            float4 b = *(const float4*)&Kt[d * 68 + tx * 4];
            float ar[4] = {a.x, a.y, a.z, a.w};
            float br[4] = {b.x, b.y, b.z, b.w};
            #pragma unroll
            for (int i = 0; i < 4; i++)
                #pragma unroll
                for (int j = 0; j < 4; j++) s[i][j] += ar[i] * br[j];
        }

        // write S^T to smem with causal mask (only diagonal tile masks)
        const bool diag = (t == blockIdx.x);   // j0 == m0
        #pragma unroll
        for (int i = 0; i < 4; i++) {
            int r = ty * 4 + i;
            #pragma unroll
            for (int j = 0; j < 4; j++) {
                int c = tx * 4 + j;
                float v = s[i][j];
                if (diag && c > r) v = -1e30f;
                Ps[c * 68 + r] = v;
            }
        }
        __syncthreads();

        // softmax phase 1: per-quarter row max
        {
            const int r = tid & 63, q = tid >> 6;
            float mx = -1e30f;
            #pragma unroll
            for (int c = q * 16; c < q * 16 + 16; c++)
                mx = fmaxf(mx, Ps[c * 68 + r]);
            qmax[q * 64 + r] = mx;
        }
        __syncthreads();
        if (tid < 64) {
            const int r = tid;
            float mx = fmaxf(fmaxf(qmax[r], qmax[64 + r]),
                             fmaxf(qmax[128 + r], qmax[192 + r]));
            float mold = rm[r];
            float mnew = fmaxf(mold, mx);
            rm[r] = mnew;
            ral[r] = __expf(mold - mnew);
        }
        __syncthreads();
        // softmax phase 2: exponentiate + partial sums
        {
            const int r = tid & 63, q = tid >> 6;
            const float mnew = rm[r];
            float ssum = 0.f;
            #pragma unroll
            for (int c = q * 16; c < q * 16 + 16; c++) {
                float p = __expf(Ps[c * 68 + r] - mnew);
                Ps[c * 68 + r] = p;
                ssum += p;
            }
            qsum[q * 64 + r] = ssum;
        }
        __syncthreads();
        if (tid < 64) {
            const int r = tid;
            rl[r] = rl[r] * ral[r] +
                    (qsum[r] + qsum[64 + r]) + (qsum[128 + r] + qsum[192 + r]);
        }

        // rescale accumulator + O += P @ V
        float al[4];
        #pragma unroll
        for (int i = 0; i < 4; i++) al[i] = ral[ty * 4 + i];
        #pragma unroll
        for (int i = 0; i < 4; i++)
            #pragma unroll
            for (int j = 0; j < 4; j++) o[i][j] *= al[i];
        #pragma unroll
        for (int c = 0; c < 64; c++) {
            float4 pv = *(const float4*)&Ps[c * 68 + ty * 4];
            float4 vv = *(const float4*)&Vs[c * 64 + tx * 4];
            float pr[4] = {pv.x, pv.y, pv.z, pv.w};
            float vr[4] = {vv.x, vv.y, vv.z, vv.w};
            #pragma unroll
            for (int i = 0; i < 4; i++)
                #pragma unroll
                for (int j = 0; j < 4; j++) o[i][j] += pr[i] * vr[j];
        }
    }
    __syncthreads();   // rl final values visible

    #pragma unroll
    for (int i = 0; i < 4; i++) {
        const int r = ty * 4 + i;
        const float linv = 1.0f / rl[r];
        float4 ov;
        ov.x = o[i][0] * linv;
        ov.y = o[i][1] * linv;
        ov.z = o[i][2] * linv;
        ov.w = o[i][3] * linv;
        *(float4*)&ob[(size_t)(m0 + r) * Dh_ + tx * 4] = ov;
    }
}

// ---------------------------------------------------------------------------
extern "C" void kernel_launch(void* const* d_in, const int* in_sizes, int n_in,
                              void* d_out, int out_size)
{
    const float* x   = (const float*)d_in[0];
    const float* Wq  = (const float*)d_in[1];
    const float* Wkv = (const float*)d_in[2];
    const float* Wo  = (const float*)d_in[3];
    const float* bo  = (const float*)d_in[4];
    float* out = (float*)d_out;

    cudaFuncSetAttribute(flash_k, cudaFuncAttributeMaxDynamicSharedMemorySize,
                         FL_SMEM_BYTES);

    dim3 blk(256);
    gemm_k<0><<<dim3(DIM_ / 128, M_ / 128), blk>>>(x, Wq, nullptr, nullptr, DIM_);
    gemm_k<1><<<dim3(2 * DIM_ / 128, M_ / 128), blk>>>(x, Wkv, nullptr, nullptr, 2 * DIM_);
    flash_k<<<dim3(N_ / 64, B_ * H_), blk, FL_SMEM_BYTES>>>();
    gemm_k<2><<<dim3(DIM_ / 128, M_ / 128), blk>>>(nullptr, Wo, out, bo, DIM_);
}

// round 4
// speedup vs baseline: 2.4587x; 2.4587x over previous
#include <cuda_runtime.h>
#include <cstdint>
#include <math.h>

#define B_  4
#define H_  16
#define N_  2048
#define Dh_ 64
#define DIM_ 1024
#define M_  (B_*N_)          // 8192
#define ELEMS (B_*H_*N_*Dh_) // 8388608

__device__ float g_q[ELEMS];
__device__ float g_k[ELEMS];
__device__ float g_v[ELEMS];
__device__ float g_o[ELEMS];

// f32 -> tf32 (round-to-nearest on 10-bit mantissa), bits in a u32
__device__ __forceinline__ uint32_t f2tf(float f) {
    uint32_t u;
    asm("cvt.rna.tf32.f32 %0, %1;" : "=r"(u) : "f"(f));
    return u;
}
__device__ __forceinline__ float f2tf_f(float f) {
    return __uint_as_float(f2tf(f));
}

#define MMA_TF32(c, a, b) \
    asm volatile("mma.sync.aligned.m16n8k8.row.col.f32.tf32.tf32.f32 " \
        "{%0,%1,%2,%3},{%4,%5,%6,%7},{%8,%9},{%0,%1,%2,%3};" \
        : "+f"((c)[0]), "+f"((c)[1]), "+f"((c)[2]), "+f"((c)[3]) \
        : "r"((a)[0]), "r"((a)[1]), "r"((a)[2]), "r"((a)[3]), \
          "r"((b)[0]), "r"((b)[1]))

// ---------------------------------------------------------------------------
// tf32 mma GEMM: C[8192 x Ncols] = A[8192 x 1024] @ W[1024 x Ncols]
// BM=128, BN=128, BK=16, 256 thr = 8 warps (4M x 2N), warp tile 32x64.
// A-fragment order (PTX): a0=(r,k) a1=(r+8,k) a2=(r,k+4) a3=(r+8,k+4)
// ---------------------------------------------------------------------------
#define AP 136   // pitch for [k][m] / [k][n] smem tiles

template<int MODE>
__global__ void __launch_bounds__(256, 2)
mma_gemm(const float* __restrict__ A, const float* __restrict__ W,
         float* __restrict__ Cout, const float* __restrict__ bias, int Ncols)
{
    __shared__ float As[2][16 * AP];
    __shared__ float Bs[2][16 * AP];

    const int tid = threadIdx.x;
    const int wid = tid >> 5, lane = tid & 31;
    const int m0 = blockIdx.y * 128;
    const int n0 = blockIdx.x * 128;
    const int warp_row = (wid & 3) * 32;
    const int warp_col = (wid >> 2) * 64;

    const int lm = tid >> 1;            // A row 0..127
    const int lq = tid & 1;             // which 8-col half
    const int bk = tid >> 4;            // B row 0..15
    const int bc = tid & 15;            // B col group

    float acc[2][8][4];
    #pragma unroll
    for (int f = 0; f < 2; f++)
        #pragma unroll
        for (int g = 0; g < 8; g++)
            #pragma unroll
            for (int i = 0; i < 4; i++) acc[f][g][i] = 0.f;

    float4 a_st[2], b_st[2];

    auto ldg_tile = [&](int t) {
        const int k0 = t * 16;
        #pragma unroll
        for (int it = 0; it < 2; it++) {
            const int kk = (lq * 2 + it) * 4;
            if (MODE == 2) {
                int gm = m0 + lm;
                int b = gm >> 11, nn = gm & 2047;
                int k = k0 + kk, h = k >> 6, d = k & 63;
                a_st[it] = *(const float4*)&g_o[(((size_t)((b << 4) + h)) * N_ + nn) * Dh_ + d];
            } else {
                a_st[it] = *(const float4*)&A[(size_t)(m0 + lm) * DIM_ + k0 + kk];
            }
        }
        #pragma unroll
        for (int it = 0; it < 2; it++) {
            const int nn = it * 64 + bc * 4;
            b_st[it] = *(const float4*)&W[(size_t)(k0 + bk) * Ncols + n0 + nn];
        }
    };
    auto sts_tile = [&](int p) {
        #pragma unroll
        for (int it = 0; it < 2; it++) {
            const int kk = (lq * 2 + it) * 4;
            float* s = As[p];
            s[(kk + 0) * AP + lm] = f2tf_f(a_st[it].x);
            s[(kk + 1) * AP + lm] = f2tf_f(a_st[it].y);
            s[(kk + 2) * AP + lm] = f2tf_f(a_st[it].z);
            s[(kk + 3) * AP + lm] = f2tf_f(a_st[it].w);
        }
        #pragma unroll
        for (int it = 0; it < 2; it++) {
            const int nn = it * 64 + bc * 4;
            float4 v;
            v.x = f2tf_f(b_st[it].x);
            v.y = f2tf_f(b_st[it].y);
            v.z = f2tf_f(b_st[it].z);
            v.w = f2tf_f(b_st[it].w);
            *(float4*)&Bs[p][bk * AP + nn] = v;
        }
    };

    ldg_tile(0);
    sts_tile(0);
    __syncthreads();

    const int l4 = lane >> 2;   // 0..7
    const int lk = lane & 3;    // 0..3

    for (int t = 0; t < DIM_ / 16; t++) {
        const int p = t & 1;
        if (t + 1 < DIM_ / 16) ldg_tile(t + 1);

        #pragma unroll
        for (int ks = 0; ks < 16; ks += 8) {
            const int kb = ks + lk;
            uint32_t af[2][4];
            #pragma unroll
            for (int f = 0; f < 2; f++) {
                const int row = warp_row + f * 16 + l4;
                af[f][0] = __float_as_uint(As[p][kb * AP + row]);          // (r,   k)
                af[f][1] = __float_as_uint(As[p][kb * AP + row + 8]);      // (r+8, k)
                af[f][2] = __float_as_uint(As[p][(kb + 4) * AP + row]);    // (r,   k+4)
                af[f][3] = __float_as_uint(As[p][(kb + 4) * AP + row + 8]);// (r+8, k+4)
            }
            #pragma unroll
            for (int g = 0; g < 8; g++) {
                const int col = warp_col + g * 8 + l4;
                uint32_t bf[2];
                bf[0] = __float_as_uint(Bs[p][kb * AP + col]);
                bf[1] = __float_as_uint(Bs[p][(kb + 4) * AP + col]);
                MMA_TF32(acc[0][g], af[0], bf);
                MMA_TF32(acc[1][g], af[1], bf);
            }
        }
        if (t + 1 < DIM_ / 16) sts_tile(p ^ 1);
        __syncthreads();
    }

    // epilogue
    const int r0 = m0 + warp_row + l4;
    const int c0 = n0 + warp_col + lk * 2;
    #pragma unroll
    for (int f = 0; f < 2; f++) {
        #pragma unroll
        for (int g = 0; g < 8; g++) {
            const int n = c0 + g * 8;
            #pragma unroll
            for (int half = 0; half < 2; half++) {
                const int m = r0 + f * 16 + half * 8;
                float2 v;
                v.x = acc[f][g][half * 2 + 0];
                v.y = acc[f][g][half * 2 + 1];
                if (MODE == 2) {
                    v.x += bias[n];
                    v.y += bias[n + 1];
                    *(float2*)&Cout[(size_t)m * DIM_ + n] = v;
                } else {
                    const int b = m >> 11, nn = m & 2047;
                    if (MODE == 0) {
                        v.x *= 0.125f; v.y *= 0.125f;
                        const int h = n >> 6, d = n & 63;
                        *(float2*)&g_q[(((size_t)((b << 4) + h)) * N_ + nn) * Dh_ + d] = v;
                    } else {
                        float* dst = (n < 1024) ? g_k : g_v;
                        const int cc = n & 1023;
                        const int h = cc >> 6, d = cc & 63;
                        *(float2*)&dst[(((size_t)((b << 4) + h)) * N_ + nn) * Dh_ + d] = v;
                    }
                }
            }
        }
    }
}

// ---------------------------------------------------------------------------
// Flash attention, causal, tf32 mma. Block = 64 q-rows of one (b,h).
// 256 thr = 8 warps (4M x 2N). Qs[d][i], Ks[d][j], Vs[j][d], Ps[j][i], pitch 72.
// ---------------------------------------------------------------------------
#define FP 72
#define FL_SMEM_FLOATS (4*64*FP + 3*64 + 2*256)
#define FL_SMEM_BYTES  (FL_SMEM_FLOATS * 4)

__global__ void __launch_bounds__(256) flash_k()
{
    extern __shared__ __align__(16) float sm[];
    float* Qs = sm;                 // [64][FP]  Qs[d*FP + i]
    float* Ks = Qs + 64 * FP;       // [64][FP]  Ks[d*FP + j]
    float* Vs = Ks + 64 * FP;       // [64][FP]  Vs[j*FP + d]
    float* Ps = Vs + 64 * FP;       // [64][FP]  Ps[j*FP + i]
    float* rm = Ps + 64 * FP;       // [64]
    float* rl = rm + 64;            // [64]
    float* ral = rl + 64;           // [64]
    float* qmax = ral + 64;         // [4][64]
    float* qsum = qmax + 256;       // [4][64]

    const int tid = threadIdx.x;
    const int bh = blockIdx.y;
    const int m0 = blockIdx.x * 64;

    const float* qb = g_q + (size_t)bh * N_ * Dh_;
    const float* kb = g_k + (size_t)bh * N_ * Dh_;
    const float* vb = g_v + (size_t)bh * N_ * Dh_;
    float* ob = g_o + (size_t)bh * N_ * Dh_;

    const int lr = tid >> 2;             // 0..63 row for loads
    const int dbase = (tid & 3) * 4;

    // Q -> Qs[d][i], tf32-rounded
    #pragma unroll
    for (int dd = 0; dd < 4; dd++) {
        const int d4 = dbase + dd * 16;
        float4 qv = *(const float4*)&qb[(size_t)(m0 + lr) * Dh_ + d4];
        Qs[(d4 + 0) * FP + lr] = f2tf_f(qv.x);
        Qs[(d4 + 1) * FP + lr] = f2tf_f(qv.y);
        Qs[(d4 + 2) * FP + lr] = f2tf_f(qv.z);
        Qs[(d4 + 3) * FP + lr] = f2tf_f(qv.w);
    }
    if (tid < 64) { rm[tid] = -1e30f; rl[tid] = 0.f; }

    const int wid = tid >> 5, lane = tid & 31;
    const int warp_m = (wid & 3) * 16;
    const int warp_n = (wid >> 2) * 32;
    const int l4 = lane >> 2, lk = lane & 3;
    const int i0 = warp_m + l4;

    float o[4][4];
    #pragma unroll
    for (int g = 0; g < 4; g++)
        #pragma unroll
        for (int i = 0; i < 4; i++) o[g][i] = 0.f;

    const int ntiles = blockIdx.x + 1;
    for (int t = 0; t < ntiles; t++) {
        const int j0 = t * 64;
        __syncthreads();
        // K -> Ks[d][j], V -> Vs[j][d], tf32-rounded
        #pragma unroll
        for (int dd = 0; dd < 4; dd++) {
            const int d4 = dbase + dd * 16;
            float4 kv = *(const float4*)&kb[(size_t)(j0 + lr) * Dh_ + d4];
            Ks[(d4 + 0) * FP + lr] = f2tf_f(kv.x);
            Ks[(d4 + 1) * FP + lr] = f2tf_f(kv.y);
            Ks[(d4 + 2) * FP + lr] = f2tf_f(kv.z);
            Ks[(d4 + 3) * FP + lr] = f2tf_f(kv.w);
            float4 vv = *(const float4*)&vb[(size_t)(j0 + lr) * Dh_ + d4];
            float4 vt;
            vt.x = f2tf_f(vv.x); vt.y = f2tf_f(vv.y);
            vt.z = f2tf_f(vv.z); vt.w = f2tf_f(vv.w);
            *(float4*)&Vs[lr * FP + d4] = vt;
        }
        __syncthreads();

        // S = Q K^T  (mma)
        float s[4][4];
        #pragma unroll
        for (int g = 0; g < 4; g++)
            #pragma unroll
            for (int i = 0; i < 4; i++) s[g][i] = 0.f;
        #pragma unroll
        for (int ks = 0; ks < 64; ks += 8) {
            const int kk = ks + lk;
            uint32_t aq[4];
            aq[0] = __float_as_uint(Qs[kk * FP + i0]);            // (i0,   k)
            aq[1] = __float_as_uint(Qs[kk * FP + i0 + 8]);        // (i0+8, k)
            aq[2] = __float_as_uint(Qs[(kk + 4) * FP + i0]);      // (i0,   k+4)
            aq[3] = __float_as_uint(Qs[(kk + 4) * FP + i0 + 8]);  // (i0+8, k+4)
            #pragma unroll
            for (int g = 0; g < 4; g++) {
                const int col = warp_n + g * 8 + l4;
                uint32_t bq[2];
                bq[0] = __float_as_uint(Ks[kk * FP + col]);
                bq[1] = __float_as_uint(Ks[(kk + 4) * FP + col]);
                MMA_TF32(s[g], aq, bq);
            }
        }

        // write S^T into Ps[j][i] with causal mask on the diagonal tile
        // c0=(i0,j) c1=(i0,j+1) c2=(i0+8,j) c3=(i0+8,j+1)
        const bool diag = (t == blockIdx.x);
        #pragma unroll
        for (int g = 0; g < 4; g++) {
            const int j = warp_n + g * 8 + lk * 2;
            float v0 = s[g][0], v1 = s[g][1], v2 = s[g][2], v3 = s[g][3];
            if (diag) {
                if (j     > i0)     v0 = -1e30f;
                if (j + 1 > i0)     v1 = -1e30f;
                if (j     > i0 + 8) v2 = -1e30f;
                if (j + 1 > i0 + 8) v3 = -1e30f;
            }
            Ps[j * FP + i0]           = v0;
            Ps[(j + 1) * FP + i0]     = v1;
            Ps[j * FP + i0 + 8]       = v2;
            Ps[(j + 1) * FP + i0 + 8] = v3;
        }
        __syncthreads();

        // softmax phase 1: per-quarter row max
        {
            const int r = tid & 63, q = tid >> 6;
            float mx = -1e30f;
            #pragma unroll
            for (int c = q * 16; c < q * 16 + 16; c++)
                mx = fmaxf(mx, Ps[c * FP + r]);
            qmax[q * 64 + r] = mx;
        }
        __syncthreads();
        if (tid < 64) {
            const int r = tid;
            float mx = fmaxf(fmaxf(qmax[r], qmax[64 + r]),
                             fmaxf(qmax[128 + r], qmax[192 + r]));
            float mold = rm[r];
            float mnew = fmaxf(mold, mx);
            rm[r] = mnew;
            ral[r] = __expf(mold - mnew);
        }
        __syncthreads();
        // softmax phase 2: exp (store tf32-rounded P) + partial sums
        {
            const int r = tid & 63, q = tid >> 6;
            const float mnew = rm[r];
            float ssum = 0.f;
            #pragma unroll
            for (int c = q * 16; c < q * 16 + 16; c++) {
                float p = __expf(Ps[c * FP + r] - mnew);
                Ps[c * FP + r] = f2tf_f(p);
                ssum += p;
            }
            qsum[q * 64 + r] = ssum;
        }
        __syncthreads();
        if (tid < 64) {
            const int r = tid;
            rl[r] = rl[r] * ral[r] +
                    (qsum[r] + qsum[64 + r]) + (qsum[128 + r] + qsum[192 + r]);
        }

        // rescale accumulator, then O += P @ V (mma)
        const float al0 = ral[i0], al1 = ral[i0 + 8];
        #pragma unroll
        for (int g = 0; g < 4; g++) {
            o[g][0] *= al0; o[g][1] *= al0;
            o[g][2] *= al1; o[g][3] *= al1;
        }
        #pragma unroll
        for (int ks = 0; ks < 64; ks += 8) {
            const int kk = ks + lk;
            uint32_t ap[4];
            ap[0] = __float_as_uint(Ps[kk * FP + i0]);            // (i0,   k)
            ap[1] = __float_as_uint(Ps[kk * FP + i0 + 8]);        // (i0+8, k)
            ap[2] = __float_as_uint(Ps[(kk + 4) * FP + i0]);      // (i0,   k+4)
            ap[3] = __float_as_uint(Ps[(kk + 4) * FP + i0 + 8]);  // (i0+8, k+4)
            #pragma unroll
            for (int g = 0; g < 4; g++) {
                const int col = warp_n + g * 8 + l4;
                uint32_t bv[2];
                bv[0] = __float_as_uint(Vs[kk * FP + col]);
                bv[1] = __float_as_uint(Vs[(kk + 4) * FP + col]);
                MMA_TF32(o[g], ap, bv);
            }
        }
    }
    __syncthreads();

    const float linv0 = 1.0f / rl[i0];
    const float linv1 = 1.0f / rl[i0 + 8];
    #pragma unroll
    for (int g = 0; g < 4; g++) {
        const int d = warp_n + g * 8 + lk * 2;
        float2 v0, v1;
        v0.x = o[g][0] * linv0; v0.y = o[g][1] * linv0;
        v1.x = o[g][2] * linv1; v1.y = o[g][3] * linv1;
        *(float2*)&ob[(size_t)(m0 + i0) * Dh_ + d] = v0;
        *(float2*)&ob[(size_t)(m0 + i0 + 8) * Dh_ + d] = v1;
    }
}

// ---------------------------------------------------------------------------
extern "C" void kernel_launch(void* const* d_in, const int* in_sizes, int n_in,
                              void* d_out, int out_size)
{
    const float* x   = (const float*)d_in[0];
    const float* Wq  = (const float*)d_in[1];
    const float* Wkv = (const float*)d_in[2];
    const float* Wo  = (const float*)d_in[3];
    const float* bo  = (const float*)d_in[4];
    float* out = (float*)d_out;

    static bool attr_done = false;
    if (!attr_done) {
        cudaFuncSetAttribute(flash_k, cudaFuncAttributeMaxDynamicSharedMemorySize,
                             FL_SMEM_BYTES);
        attr_done = true;
    }

    dim3 blk(256);
    mma_gemm<0><<<dim3(DIM_ / 128, M_ / 128), blk>>>(x, Wq, nullptr, nullptr, DIM_);
    mma_gemm<1><<<dim3(2 * DIM_ / 128, M_ / 128), blk>>>(x, Wkv, nullptr, nullptr, 2 * DIM_);
    flash_k<<<dim3(N_ / 64, B_ * H_), blk, FL_SMEM_BYTES>>>();
    mma_gemm<2><<<dim3(DIM_ / 128, M_ / 128), blk>>>(nullptr, Wo, out, bo, DIM_);
}

// round 5
// speedup vs baseline: 3.0900x; 1.2568x over previous
#include <cuda_runtime.h>
#include <cstdint>
#include <math.h>

#define B_  4
#define H_  16
#define N_  2048
#define Dh_ 64
#define DIM_ 1024
#define M_  (B_*N_)          // 8192
#define ELEMS (B_*H_*N_*Dh_) // 8388608

__device__ __align__(16) float g_q[ELEMS];
__device__ __align__(16) float g_k[ELEMS];
__device__ __align__(16) float g_v[ELEMS];
__device__ __align__(16) float g_o[ELEMS];

// f32 -> tf32 (round-to-nearest on 10-bit mantissa)
__device__ __forceinline__ uint32_t f2tf(float f) {
    uint32_t u;
    asm("cvt.rna.tf32.f32 %0, %1;" : "=r"(u) : "f"(f));
    return u;
}
__device__ __forceinline__ float f2tf_f(float f) {
    return __uint_as_float(f2tf(f));
}
__device__ __forceinline__ uint32_t smem_u32(const void* p) {
    uint32_t a;
    asm("{ .reg .u64 t; cvta.to.shared.u64 t, %1; cvt.u32.u64 %0, t; }"
        : "=r"(a) : "l"(p));
    return a;
}

#define MMA_TF32(c, a, b) \
    asm volatile("mma.sync.aligned.m16n8k8.row.col.f32.tf32.tf32.f32 " \
        "{%0,%1,%2,%3},{%4,%5,%6,%7},{%8,%9},{%0,%1,%2,%3};" \
        : "+f"((c)[0]), "+f"((c)[1]), "+f"((c)[2]), "+f"((c)[3]) \
        : "r"((a)[0]), "r"((a)[1]), "r"((a)[2]), "r"((a)[3]), \
          "r"((b)[0]), "r"((b)[1]))

// ---------------------------------------------------------------------------
// tf32 mma GEMM (unchanged from R4 except MODE 0/1 epilogues store
// tf32-rounded values so flash can consume them without conversion).
// ---------------------------------------------------------------------------
#define AP 136

template<int MODE>
__global__ void __launch_bounds__(256, 2)
mma_gemm(const float* __restrict__ A, const float* __restrict__ W,
         float* __restrict__ Cout, const float* __restrict__ bias, int Ncols)
{
    __shared__ float As[2][16 * AP];
    __shared__ float Bs[2][16 * AP];

    const int tid = threadIdx.x;
    const int wid = tid >> 5, lane = tid & 31;
    const int m0 = blockIdx.y * 128;
    const int n0 = blockIdx.x * 128;
    const int warp_row = (wid & 3) * 32;
    const int warp_col = (wid >> 2) * 64;

    const int lm = tid >> 1;
    const int lq = tid & 1;
    const int bk = tid >> 4;
    const int bc = tid & 15;

    float acc[2][8][4];
    #pragma unroll
    for (int f = 0; f < 2; f++)
        #pragma unroll
        for (int g = 0; g < 8; g++)
            #pragma unroll
            for (int i = 0; i < 4; i++) acc[f][g][i] = 0.f;

    float4 a_st[2], b_st[2];

    auto ldg_tile = [&](int t) {
        const int k0 = t * 16;
        #pragma unroll
        for (int it = 0; it < 2; it++) {
            const int kk = (lq * 2 + it) * 4;
            if (MODE == 2) {
                int gm = m0 + lm;
                int b = gm >> 11, nn = gm & 2047;
                int k = k0 + kk, h = k >> 6, d = k & 63;
                a_st[it] = *(const float4*)&g_o[(((size_t)((b << 4) + h)) * N_ + nn) * Dh_ + d];
            } else {
                a_st[it] = *(const float4*)&A[(size_t)(m0 + lm) * DIM_ + k0 + kk];
            }
        }
        #pragma unroll
        for (int it = 0; it < 2; it++) {
            const int nn = it * 64 + bc * 4;
            b_st[it] = *(const float4*)&W[(size_t)(k0 + bk) * Ncols + n0 + nn];
        }
    };
    auto sts_tile = [&](int p) {
        #pragma unroll
        for (int it = 0; it < 2; it++) {
            const int kk = (lq * 2 + it) * 4;
            float* s = As[p];
            s[(kk + 0) * AP + lm] = f2tf_f(a_st[it].x);
            s[(kk + 1) * AP + lm] = f2tf_f(a_st[it].y);
            s[(kk + 2) * AP + lm] = f2tf_f(a_st[it].z);
            s[(kk + 3) * AP + lm] = f2tf_f(a_st[it].w);
        }
        #pragma unroll
        for (int it = 0; it < 2; it++) {
            const int nn = it * 64 + bc * 4;
            float4 v;
            v.x = f2tf_f(b_st[it].x);
            v.y = f2tf_f(b_st[it].y);
            v.z = f2tf_f(b_st[it].z);
            v.w = f2tf_f(b_st[it].w);
            *(float4*)&Bs[p][bk * AP + nn] = v;
        }
    };

    ldg_tile(0);
    sts_tile(0);
    __syncthreads();

    const int l4 = lane >> 2;
    const int lk = lane & 3;

    for (int t = 0; t < DIM_ / 16; t++) {
        const int p = t & 1;
        if (t + 1 < DIM_ / 16) ldg_tile(t + 1);

        #pragma unroll
        for (int ks = 0; ks < 16; ks += 8) {
            const int kb = ks + lk;
            uint32_t af[2][4];
            #pragma unroll
            for (int f = 0; f < 2; f++) {
                const int row = warp_row + f * 16 + l4;
                af[f][0] = __float_as_uint(As[p][kb * AP + row]);
                af[f][1] = __float_as_uint(As[p][kb * AP + row + 8]);
                af[f][2] = __float_as_uint(As[p][(kb + 4) * AP + row]);
                af[f][3] = __float_as_uint(As[p][(kb + 4) * AP + row + 8]);
            }
            #pragma unroll
            for (int g = 0; g < 8; g++) {
                const int col = warp_col + g * 8 + l4;
                uint32_t bf[2];
                bf[0] = __float_as_uint(Bs[p][kb * AP + col]);
                bf[1] = __float_as_uint(Bs[p][(kb + 4) * AP + col]);
                MMA_TF32(acc[0][g], af[0], bf);
                MMA_TF32(acc[1][g], af[1], bf);
            }
        }
        if (t + 1 < DIM_ / 16) sts_tile(p ^ 1);
        __syncthreads();
    }

    const int r0 = m0 + warp_row + l4;
    const int c0 = n0 + warp_col + lk * 2;
    #pragma unroll
    for (int f = 0; f < 2; f++) {
        #pragma unroll
        for (int g = 0; g < 8; g++) {
            const int n = c0 + g * 8;
            #pragma unroll
            for (int half = 0; half < 2; half++) {
                const int m = r0 + f * 16 + half * 8;
                float2 v;
                v.x = acc[f][g][half * 2 + 0];
                v.y = acc[f][g][half * 2 + 1];
                if (MODE == 2) {
                    v.x += bias[n];
                    v.y += bias[n + 1];
                    *(float2*)&Cout[(size_t)m * DIM_ + n] = v;
                } else {
                    const int b = m >> 11, nn = m & 2047;
                    if (MODE == 0) {
                        v.x = f2tf_f(v.x * 0.125f);
                        v.y = f2tf_f(v.y * 0.125f);
                        const int h = n >> 6, d = n & 63;
                        *(float2*)&g_q[(((size_t)((b << 4) + h)) * N_ + nn) * Dh_ + d] = v;
                    } else {
                        v.x = f2tf_f(v.x);
                        v.y = f2tf_f(v.y);
                        float* dst = (n < 1024) ? g_k : g_v;
                        const int cc = n & 1023;
                        const int h = cc >> 6, d = cc & 63;
                        *(float2*)&dst[(((size_t)((b << 4) + h)) * N_ + nn) * Dh_ + d] = v;
                    }
                }
            }
        }
    }
}

// ---------------------------------------------------------------------------
// Flash attention v2: FA2-style. Block = 128 q-rows, 8 warps x 16 rows.
// Warp-local online softmax (shfl within lane quads), Q fragments in regs,
// P via per-warp fragment-packed smem patch, cp.async double-buffered K/V.
// K pitch 68 (banks l4*4+lk), V pitch 72 (banks lk*8+l4): conflict-free.
// ---------------------------------------------------------------------------
#define KSP 68
#define VSP 72
#define KS_ST (64*KSP)            // 4352 floats
#define VS_ST (64*VSP)            // 4608 floats
#define SMV  (2*KS_ST)            // 8704
#define SMP  (SMV + 2*VS_ST)      // 17920
#define FL2_FLOATS (SMP + 8*512)  // 22016
#define FL2_BYTES  (FL2_FLOATS*4) // 88064

__global__ void __launch_bounds__(256, 2) flash2_k()
{
    extern __shared__ __align__(16) float sm[];
    const int tid = threadIdx.x;
    const int bh = blockIdx.y;
    const int rb = gridDim.x - 1 - blockIdx.x;   // big blocks launch first
    const int m0 = rb * 128;

    const float* qb = g_q + (size_t)bh * N_ * Dh_;
    const float* kb = g_k + (size_t)bh * N_ * Dh_;
    const float* vb = g_v + (size_t)bh * N_ * Dh_;
    float* ob = g_o + (size_t)bh * N_ * Dh_;

    const int wid = tid >> 5, lane = tid & 31;
    const int l4 = lane >> 2, lk = lane & 3;
    const int R0 = m0 + wid * 16;

    const uint32_t smb = smem_u32(sm);
    float* Pw = sm + SMP + wid * 512;

    // Q fragments in registers (values already tf32-exact from projection)
    uint32_t aq[8][4];
    {
        const float* q0 = qb + (size_t)(R0 + l4) * Dh_;
        const float* q1 = qb + (size_t)(R0 + l4 + 8) * Dh_;
        #pragma unroll
        for (int ks = 0; ks < 8; ks++) {
            const int d = ks * 8 + lk;
            aq[ks][0] = __float_as_uint(q0[d]);
            aq[ks][1] = __float_as_uint(q1[d]);
            aq[ks][2] = __float_as_uint(q0[d + 4]);
            aq[ks][3] = __float_as_uint(q1[d + 4]);
        }
    }

    float o[8][4];
    #pragma unroll
    for (int dg = 0; dg < 8; dg++)
        #pragma unroll
        for (int i = 0; i < 4; i++) o[dg][i] = 0.f;
    float mr0 = -1e30f, mr1 = -1e30f, lr0 = 0.f, lr1 = 0.f;

    const int ntiles = 2 * rb + 2;
    const int jr = tid >> 2;       // loader row 0..63
    const int cb = tid & 3;        // loader chunk base

    auto load_tile = [&](int t, int s) {
        const int j0 = t * 64;
        const float* krow = kb + (size_t)(j0 + jr) * Dh_;
        const float* vrow = vb + (size_t)(j0 + jr) * Dh_;
        const uint32_t kd0 = smb + (uint32_t)(s * KS_ST + jr * KSP) * 4;
        const uint32_t vd0 = smb + (uint32_t)(SMV + s * VS_ST + jr * VSP) * 4;
        #pragma unroll
        for (int i = 0; i < 4; i++) {
            const int d4 = (cb + i * 4) * 4;
            asm volatile("cp.async.cg.shared.global [%0], [%1], 16;"
                         :: "r"(kd0 + d4 * 4), "l"(krow + d4));
            asm volatile("cp.async.cg.shared.global [%0], [%1], 16;"
                         :: "r"(vd0 + d4 * 4), "l"(vrow + d4));
        }
    };

    load_tile(0, 0);
    asm volatile("cp.async.commit_group;" ::: "memory");
    load_tile(1, 1);
    asm volatile("cp.async.commit_group;" ::: "memory");

    const int row0 = R0 + l4;
    const int row1 = R0 + l4 + 8;

    for (int t = 0; t < ntiles; t++) {
        const int s = t & 1;
        asm volatile("cp.async.wait_group 1;" ::: "memory");
        __syncthreads();

        if (t * 64 <= R0 + 15) {
            const float* Ksm = sm + s * KS_ST;
            const float* Vsm = sm + SMV + s * VS_ST;
            #pragma unroll
            for (int jc = 0; jc < 2; jc++) {
                const int j0c = t * 64 + jc * 32;
                if (j0c > R0 + 15) break;

                // ---- S = Q K^T over 32 cols ----
                float s4[4][4];
                #pragma unroll
                for (int jg = 0; jg < 4; jg++)
                    #pragma unroll
                    for (int i = 0; i < 4; i++) s4[jg][i] = 0.f;
                #pragma unroll
                for (int ks = 0; ks < 8; ks++) {
                    const int d = ks * 8 + lk;
                    #pragma unroll
                    for (int jg = 0; jg < 4; jg++) {
                        const int krow_s = (jc * 32 + jg * 8 + l4) * KSP;
                        uint32_t bq[2];
                        bq[0] = __float_as_uint(Ksm[krow_s + d]);
                        bq[1] = __float_as_uint(Ksm[krow_s + d + 4]);
                        MMA_TF32(s4[jg], aq[ks], bq);
                    }
                }

                // ---- causal mask (only near-diagonal chunks) ----
                if (j0c + 31 > R0) {
                    #pragma unroll
                    for (int jg = 0; jg < 4; jg++) {
                        const int jb = j0c + jg * 8 + 2 * lk;
                        if (jb     > row0) s4[jg][0] = -1e30f;
                        if (jb + 1 > row0) s4[jg][1] = -1e30f;
                        if (jb     > row1) s4[jg][2] = -1e30f;
                        if (jb + 1 > row1) s4[jg][3] = -1e30f;
                    }
                }

                // ---- in-register online softmax ----
                float mx0 = -1e30f, mx1 = -1e30f;
                #pragma unroll
                for (int jg = 0; jg < 4; jg++) {
                    mx0 = fmaxf(mx0, fmaxf(s4[jg][0], s4[jg][1]));
                    mx1 = fmaxf(mx1, fmaxf(s4[jg][2], s4[jg][3]));
                }
                mx0 = fmaxf(mx0, __shfl_xor_sync(0xffffffffu, mx0, 1));
                mx0 = fmaxf(mx0, __shfl_xor_sync(0xffffffffu, mx0, 2));
                mx1 = fmaxf(mx1, __shfl_xor_sync(0xffffffffu, mx1, 1));
                mx1 = fmaxf(mx1, __shfl_xor_sync(0xffffffffu, mx1, 2));

                const float mn0 = fmaxf(mr0, mx0);
                const float mn1 = fmaxf(mr1, mx1);
                const float a0 = __expf(mr0 - mn0);
                const float a1 = __expf(mr1 - mn1);
                mr0 = mn0; mr1 = mn1;

                float sum0 = 0.f, sum1 = 0.f;
                float p[4][4];
                #pragma unroll
                for (int jg = 0; jg < 4; jg++) {
                    p[jg][0] = f2tf_f(__expf(s4[jg][0] - mn0));
                    p[jg][1] = f2tf_f(__expf(s4[jg][1] - mn0));
                    p[jg][2] = f2tf_f(__expf(s4[jg][2] - mn1));
                    p[jg][3] = f2tf_f(__expf(s4[jg][3] - mn1));
                    sum0 += p[jg][0] + p[jg][1];
                    sum1 += p[jg][2] + p[jg][3];
                }
                sum0 += __shfl_xor_sync(0xffffffffu, sum0, 1);
                sum0 += __shfl_xor_sync(0xffffffffu, sum0, 2);
                sum1 += __shfl_xor_sync(0xffffffffu, sum1, 1);
                sum1 += __shfl_xor_sync(0xffffffffu, sum1, 2);
                lr0 = lr0 * a0 + sum0;
                lr1 = lr1 * a1 + sum1;

                #pragma unroll
                for (int dg = 0; dg < 8; dg++) {
                    o[dg][0] *= a0; o[dg][1] *= a0;
                    o[dg][2] *= a1; o[dg][3] *= a1;
                }

                // ---- pack P into A-fragment layout ----
                #pragma unroll
                for (int jg = 0; jg < 4; jg++) {
                    const int c0 = 2 * lk;
                    const int la = l4 * 4 + (c0 & 3);
                    const int rx = (c0 & 4) ? 2 : 0;
                    Pw[jg * 128 + la * 4 + rx]     = p[jg][0];
                    Pw[jg * 128 + la * 4 + rx + 1] = p[jg][2];
                    const int c1 = c0 + 1;
                    const int lb = l4 * 4 + (c1 & 3);
                    const int ry = (c1 & 4) ? 2 : 0;
                    Pw[jg * 128 + lb * 4 + ry]     = p[jg][1];
                    Pw[jg * 128 + lb * 4 + ry + 1] = p[jg][3];
                }
                __syncwarp();

                // ---- O += P V over this 32-col chunk ----
                #pragma unroll
                for (int ksp = 0; ksp < 4; ksp++) {
                    float4 pa4 = *(const float4*)&Pw[ksp * 128 + lane * 4];
                    uint32_t pa[4];
                    pa[0] = __float_as_uint(pa4.x);
                    pa[1] = __float_as_uint(pa4.y);
                    pa[2] = __float_as_uint(pa4.z);
                    pa[3] = __float_as_uint(pa4.w);
                    const int vr = (jc * 32 + ksp * 8 + lk) * VSP;
                    #pragma unroll
                    for (int dg = 0; dg < 8; dg++) {
                        const int vc = dg * 8 + l4;
                        uint32_t bv[2];
                        bv[0] = __float_as_uint(Vsm[vr + vc]);
                        bv[1] = __float_as_uint(Vsm[vr + 4 * VSP + vc]);
                        MMA_TF32(o[dg], pa, bv);
                    }
                }
                __syncwarp();
            }
        }
        __syncthreads();
        if (t + 2 < ntiles) load_tile(t + 2, s);
        asm volatile("cp.async.commit_group;" ::: "memory");
    }

    // ---- normalize + write O ----
    const float inv0 = 1.0f / lr0;
    const float inv1 = 1.0f / lr1;
    #pragma unroll
    for (int dg = 0; dg < 8; dg++) {
        const int col = dg * 8 + 2 * lk;
        float2 v0, v1;
        v0.x = o[dg][0] * inv0; v0.y = o[dg][1] * inv0;
        v1.x = o[dg][2] * inv1; v1.y = o[dg][3] * inv1;
        *(float2*)&ob[(size_t)row0 * Dh_ + col] = v0;
        *(float2*)&ob[(size_t)row1 * Dh_ + col] = v1;
    }
}

// ---------------------------------------------------------------------------
extern "C" void kernel_launch(void* const* d_in, const int* in_sizes, int n_in,
                              void* d_out, int out_size)
{
    const float* x   = (const float*)d_in[0];
    const float* Wq  = (const float*)d_in[1];
    const float* Wkv = (const float*)d_in[2];
    const float* Wo  = (const float*)d_in[3];
    const float* bo  = (const float*)d_in[4];
    float* out = (float*)d_out;

    static bool attr_done = false;
    if (!attr_done) {
        cudaFuncSetAttribute(flash2_k, cudaFuncAttributeMaxDynamicSharedMemorySize,
                             FL2_BYTES);
        attr_done = true;
    }

    dim3 blk(256);
    mma_gemm<0><<<dim3(DIM_ / 128, M_ / 128), blk>>>(x, Wq, nullptr, nullptr, DIM_);
    mma_gemm<1><<<dim3(2 * DIM_ / 128, M_ / 128), blk>>>(x, Wkv, nullptr, nullptr, 2 * DIM_);
    flash2_k<<<dim3(N_ / 128, B_ * H_), blk, FL2_BYTES>>>();
    mma_gemm<2><<<dim3(DIM_ / 128, M_ / 128), blk>>>(nullptr, Wo, out, bo, DIM_);
}